// round 16
// baseline (speedup 1.0000x reference)
#include <cuda_runtime.h>
#include <cuda_fp16.h>
#include <cstdint>
#include <cstddef>

// Problem constants (match reference)
#define N_NODES 50000
#define N_EDGES 800000
#define D_IN    128
#define D_HID   256
#define D_OUT   128

// ---------------------------------------------------------------------------
// Pipeline (8 launches; slot 4 = gemm_x so ncu profiles the GEMM):
//   1 count+conv : dst histogram (8 edges/thr) + x -> fp16 g_xh
//   2 scanAW     : blocks 0..195 per-block sums; blocks 196.. weights
//   3 scanC2     : per-block prefix + local scan -> metadata; clean cnt
//   4 gemm_x     : out  = xh@U3^T + c + flag*d           [PROFILED]
//   5 fill       : CSR adjacency, 8 edges/thread
//   6 gather1    : m1h[n] = fp16( invdeg[n] * sum xh[s] )
//   7 gather2    : A2h[n] = fp16( invdeg[n] * sum m1h[s] )
//   8 gemm_acc   : out += A2h@U1^T + m1h@U2^T
// ---------------------------------------------------------------------------

#define SCAN_BLOCKS ((N_NODES + 255) / 256)   // 196

// Device scratch
__device__ int    g_cnt[N_NODES];         // zero at load; scanC2 re-zeroes per replay
__device__ int    g_bsum[SCAN_BLOCKS];
__device__ int    g_rowoff[N_NODES + 1];
__device__ int    g_cursor[N_NODES];
__device__ int    g_eadj[N_EDGES];
__device__ float  g_invdeg[N_NODES];
__device__ float  g_flag[N_NODES];
__device__ __half g_xh[(size_t)N_NODES * 128];
__device__ __half g_m1h[(size_t)N_NODES * 128];
__device__ __half g_A2h[(size_t)N_NODES * 128];
// B fragments, warp-coalesced: index = (ktg*128 + n)*4 + tq
__device__ uint2  g_Upk[24 * 128 * 4];
__device__ float  g_c[128];
__device__ float  g_d[128];

// smem tile geometry (half): 128 rows x 128 cols, stride 136 (single buffer)
#define SA_STRIDE 136
#define SMEM_BYTES (128 * SA_STRIDE * 2)   // 34816 B

// ---------------------------------------------------------------------------
// helpers
// ---------------------------------------------------------------------------
__device__ __forceinline__ void mma16816h(float* d, const uint32_t* a, const uint32_t* b) {
    asm volatile(
        "mma.sync.aligned.m16n8k16.row.col.f32.f16.f16.f32 "
        "{%0,%1,%2,%3}, {%4,%5,%6,%7}, {%8,%9}, {%0,%1,%2,%3};"
        : "+f"(d[0]), "+f"(d[1]), "+f"(d[2]), "+f"(d[3])
        : "r"(a[0]), "r"(a[1]), "r"(a[2]), "r"(a[3]), "r"(b[0]), "r"(b[1]));
}
__device__ __forceinline__ uint32_t packh2(float a, float b) {
    __half2 h = __float22half2_rn(make_float2(a, b));
    return *reinterpret_cast<uint32_t*>(&h);
}
__device__ __forceinline__ float2 unpackh2(uint32_t u) {
    __half2 h = *reinterpret_cast<__half2*>(&u);
    return __half22float2(h);
}

// Per-block idx-dtype detection (int32 read as int64 -> >= 2^32 a.s.)
__device__ __forceinline__ int detect_idx64_block(const void* eidx) {
    __shared__ int s_idx64;
    if (threadIdx.x < 32) {
        const long long* p = (const long long*)eidx;
        int ok = 1;
        #pragma unroll
        for (int i = 0; i < 16; ++i) {
            long long v = p[threadIdx.x * 16 + i];
            ok &= (v >= 0 && v < (long long)N_NODES);
        }
        unsigned m = __ballot_sync(0xffffffffu, ok);
        if (threadIdx.x == 0) s_idx64 = (m == 0xffffffffu) ? 1 : 0;
    }
    __syncthreads();
    return s_idx64;
}

// load 8 indices starting at e0 (e0 multiple of 8, in-bounds)
__device__ __forceinline__ void load8_idx(const void* base, int idx64, long long off,
                                          int e0, int* d) {
    if (idx64) {
        const long long* ep = (const long long*)base + off;
        const longlong2* p = (const longlong2*)(ep + e0);
        longlong2 a = p[0], b = p[1], c = p[2], e = p[3];
        d[0] = (int)a.x; d[1] = (int)a.y; d[2] = (int)b.x; d[3] = (int)b.y;
        d[4] = (int)c.x; d[5] = (int)c.y; d[6] = (int)e.x; d[7] = (int)e.y;
    } else {
        const int* ep = (const int*)base + off;
        const int4 a = *(const int4*)(ep + e0);
        const int4 b = *(const int4*)(ep + e0 + 4);
        d[0] = a.x; d[1] = a.y; d[2] = a.z; d[3] = a.w;
        d[4] = b.x; d[5] = b.y; d[6] = b.z; d[7] = b.w;
    }
}

// ---------------------------------------------------------------------------
// count + convert
// ---------------------------------------------------------------------------
#define CONV_BLOCKS 3125   // 1.6M float4 groups / (256 thr * 2)
#define EDGE_BLOCKS8 ((N_EDGES / 8 + 255) / 256)   // 391

__global__ __launch_bounds__(256)
void count_conv_kernel(const void* __restrict__ eidx, const float* __restrict__ x) {
    const int idx64 = detect_idx64_block(eidx);
    const int tid = blockIdx.x * 256 + threadIdx.x;

    const float4* x4 = (const float4*)x;
    #pragma unroll
    for (int j = 0; j < 2; ++j) {
        const int gidx = tid + j * (CONV_BLOCKS * 256);
        if (gidx < (N_NODES * 128) / 4) {
            float4 v = x4[gidx];
            uint2 h;
            h.x = packh2(v.x, v.y);
            h.y = packh2(v.z, v.w);
            ((uint2*)g_xh)[gidx] = h;
        }
    }

    if (blockIdx.x < EDGE_BLOCKS8) {
        const int e0 = tid * 8;
        if (e0 < N_EDGES) {
            int d[8];
            load8_idx(eidx, idx64, N_EDGES, e0, d);
            #pragma unroll
            for (int j = 0; j < 8; ++j) atomicAdd(&g_cnt[d[j]], 1);
        }
    }
}

// ---------------------------------------------------------------------------
// scanAW: blocks 0..195 per-block sums; blocks 196.. weight pre-products
// ---------------------------------------------------------------------------
#define WEIGHT_ITEMS (128 * 96 + 128)                  // 12416
#define WEIGHT_BLOCKS ((WEIGHT_ITEMS + 255) / 256)     // 49

__global__ __launch_bounds__(256)
void scanAW_kernel(const float* __restrict__ Wl1,
                   const float* __restrict__ Wr1,
                   const float* __restrict__ Wl2,
                   const float* __restrict__ Wr2,
                   const float* __restrict__ b1,
                   const float* __restrict__ b2) {
    if (blockIdx.x < SCAN_BLOCKS) {
        __shared__ int ws[8];
        const int node = blockIdx.x * 256 + threadIdx.x;
        int v = (node < N_NODES) ? g_cnt[node] : 0;
        #pragma unroll
        for (int d = 16; d > 0; d >>= 1) v += __shfl_down_sync(0xffffffffu, v, d);
        if ((threadIdx.x & 31) == 0) ws[threadIdx.x >> 5] = v;
        __syncthreads();
        if (threadIdx.x < 8) {
            int s = ws[threadIdx.x];
            #pragma unroll
            for (int d = 4; d > 0; d >>= 1) s += __shfl_down_sync(0xffu, s, d);
            if (threadIdx.x == 0) g_bsum[blockIdx.x] = s;
        }
        return;
    }

    const int tid = (blockIdx.x - SCAN_BLOCKS) * 256 + threadIdx.x;
    if (tid < 128 * 96) {
        const int n   = tid / 96;
        const int rem = tid - n * 96;
        const int ktg = rem >> 2;
        const int tq  = rem & 3;
        const int seg = ktg >> 3;
        const int k0  = (ktg & 7) * 16 + 2 * tq;

        float u[4] = {0.f, 0.f, 0.f, 0.f};
        const float* A1 = Wl2 + (size_t)n * 256;
        const float* A2 = Wr2 + (size_t)n * 256;
        #pragma unroll 4
        for (int t = 0; t < 256; ++t) {
            const float wl2 = A1[t];
            const float wr2 = A2[t];
            const float* rl = Wl1 + (size_t)t * 128 + k0;
            const float* rr = Wr1 + (size_t)t * 128 + k0;
            if (seg == 0) {
                u[0] += wl2 * rl[0]; u[1] += wl2 * rl[1];
                u[2] += wl2 * rl[8]; u[3] += wl2 * rl[9];
            } else if (seg == 1) {
                u[0] += wl2 * rr[0] + wr2 * rl[0];
                u[1] += wl2 * rr[1] + wr2 * rl[1];
                u[2] += wl2 * rr[8] + wr2 * rl[8];
                u[3] += wl2 * rr[9] + wr2 * rl[9];
            } else {
                u[0] += wr2 * rr[0]; u[1] += wr2 * rr[1];
                u[2] += wr2 * rr[8]; u[3] += wr2 * rr[9];
            }
        }
        g_Upk[(ktg * 128 + n) * 4 + tq] =
            make_uint2(packh2(u[0], u[1]), packh2(u[2], u[3]));
    } else if (tid < WEIGHT_ITEMS) {
        const int a = tid - 128 * 96;
        float c = 0.f, d = 0.f;
        #pragma unroll 4
        for (int k = 0; k < 256; ++k) {
            c += Wr2[a * 256 + k] * b1[k];
            d += Wl2[a * 256 + k] * b1[k];
        }
        g_c[a] = b2[a] + c;
        g_d[a] = d;
    }
}

// ---------------------------------------------------------------------------
// scanC2: per-block prefix of g_bsum + local exclusive scan + metadata
// ---------------------------------------------------------------------------
__global__ __launch_bounds__(256)
void scanC2_kernel() {
    __shared__ int sc[256];
    __shared__ int s_boff;
    const int t = threadIdx.x;

    {
        int p = 0;
        for (int j = t; j < blockIdx.x; j += 256) p += g_bsum[j];
        #pragma unroll
        for (int d = 16; d > 0; d >>= 1) p += __shfl_down_sync(0xffffffffu, p, d);
        sc[t] = 0;
        __syncthreads();
        if ((t & 31) == 0) sc[t >> 5] = p;
        __syncthreads();
        if (t == 0) {
            int s = 0;
            #pragma unroll
            for (int w = 0; w < 8; ++w) s += sc[w];
            s_boff = s;
        }
        __syncthreads();
    }

    const int node = blockIdx.x * 256 + t;
    const int c = (node < N_NODES) ? g_cnt[node] : 0;
    sc[t] = c;
    __syncthreads();
    #pragma unroll
    for (int d = 1; d < 256; d <<= 1) {
        int add = (t >= d) ? sc[t - d] : 0;
        __syncthreads();
        sc[t] += add;
        __syncthreads();
    }
    if (node < N_NODES) {
        const int off = s_boff + sc[t] - c;
        g_rowoff[node] = off;
        g_cursor[node] = off;
        g_invdeg[node] = 1.0f / fmaxf((float)c, 1.0f);
        g_flag[node]   = (c > 0) ? 1.0f : 0.0f;
        g_cnt[node]    = 0;
    }
    if (node == N_NODES - 1) g_rowoff[N_NODES] = N_EDGES;
}

// ---------------------------------------------------------------------------
// fill: CSR adjacency, 8 edges per thread
// ---------------------------------------------------------------------------
__global__ __launch_bounds__(256)
void fill_csr_kernel(const void* __restrict__ eidx) {
    const int idx64 = detect_idx64_block(eidx);
    const int e0 = (blockIdx.x * blockDim.x + threadIdx.x) * 8;
    if (e0 >= N_EDGES) return;
    int s[8], d[8];
    load8_idx(eidx, idx64, 0, e0, s);
    load8_idx(eidx, idx64, N_EDGES, e0, d);
    int pos[8];
    #pragma unroll
    for (int j = 0; j < 8; ++j) pos[j] = atomicAdd(&g_cursor[d[j]], 1);
    #pragma unroll
    for (int j = 0; j < 8; ++j) g_eadj[pos[j]] = s[j];
}

// ---------------------------------------------------------------------------
// Gather (fp16 in/out, fp32 accum): one warp per node, lane owns 4 columns
// ---------------------------------------------------------------------------
__global__ __launch_bounds__(256)
void gather_kernel(const __half* __restrict__ src_feat, __half* __restrict__ dst_feat) {
    const int node = (blockIdx.x * blockDim.x + threadIdx.x) >> 5;
    if (node >= N_NODES) return;
    const int lane = threadIdx.x & 31;
    const int beg = g_rowoff[node];
    const int end = g_rowoff[node + 1];
    const uint2* f2 = (const uint2*)src_feat;

    float4 acc = make_float4(0.f, 0.f, 0.f, 0.f);
    int i = beg;
    for (; i + 4 <= end; i += 4) {
        const int s0 = g_eadj[i];
        const int s1 = g_eadj[i + 1];
        const int s2 = g_eadj[i + 2];
        const int s3 = g_eadj[i + 3];
        uint2 u0 = __ldg(&f2[(size_t)s0 * 32 + lane]);
        uint2 u1 = __ldg(&f2[(size_t)s1 * 32 + lane]);
        uint2 u2 = __ldg(&f2[(size_t)s2 * 32 + lane]);
        uint2 u3 = __ldg(&f2[(size_t)s3 * 32 + lane]);
        float2 a, b;
        a = unpackh2(u0.x); b = unpackh2(u0.y);
        acc.x += a.x; acc.y += a.y; acc.z += b.x; acc.w += b.y;
        a = unpackh2(u1.x); b = unpackh2(u1.y);
        acc.x += a.x; acc.y += a.y; acc.z += b.x; acc.w += b.y;
        a = unpackh2(u2.x); b = unpackh2(u2.y);
        acc.x += a.x; acc.y += a.y; acc.z += b.x; acc.w += b.y;
        a = unpackh2(u3.x); b = unpackh2(u3.y);
        acc.x += a.x; acc.y += a.y; acc.z += b.x; acc.w += b.y;
    }
    for (; i < end; ++i) {
        const int s0 = g_eadj[i];
        uint2 u0 = __ldg(&f2[(size_t)s0 * 32 + lane]);
        float2 a = unpackh2(u0.x), b = unpackh2(u0.y);
        acc.x += a.x; acc.y += a.y; acc.z += b.x; acc.w += b.y;
    }
    const float w = g_invdeg[node];
    uint2 o;
    o.x = packh2(acc.x * w, acc.y * w);
    o.y = packh2(acc.z * w, acc.w * w);
    ((uint2*)dst_feat)[(size_t)node * 32 + lane] = o;
}

// ---------------------------------------------------------------------------
// Tensor-core GEMM body, K segments [SBEG, SEND).
// WRITE: epilogue writes out + c + flag*d; else accumulates into out.
// ---------------------------------------------------------------------------
template<int SBEG, int SEND, bool WRITE>
__device__ __forceinline__
void gemm_body(const __half* s0src, const __half* s1src, const __half* s2src,
               float* __restrict__ out, int M) {
    extern __shared__ __half sA[];

    const int tid  = threadIdx.x;
    const int wid  = tid >> 5;
    const int lane = tid & 31;
    const int g    = lane >> 2;
    const int tq   = lane & 3;
    const int m0   = blockIdx.x * 128;
    const int moff = (wid >> 1) * 32;
    const int noff = (wid & 1) * 64;

    int   rows[4];
    bool  rowok[4];
    float flag[4];
    #pragma unroll
    for (int r = 0; r < 4; ++r) {
        const int mi = r >> 1, h = r & 1;
        rows[r]  = m0 + moff + mi * 16 + h * 8 + g;
        rowok[r] = rows[r] < M;
        flag[r]  = (WRITE && rowok[r]) ? g_flag[rows[r]] : 0.f;
    }

    float acc[2][8][4];
    #pragma unroll
    for (int mi = 0; mi < 2; ++mi)
        #pragma unroll
        for (int ni = 0; ni < 8; ++ni)
            #pragma unroll
            for (int q = 0; q < 4; ++q) acc[mi][ni][q] = 0.f;

    #pragma unroll 1
    for (int s = SBEG; s < SEND; ++s) {
        const __half* Asrc = (s == 0) ? s0src : ((s == 1) ? s1src : s2src);

        if (s > SBEG) __syncthreads();
        #pragma unroll 4
        for (int idx = tid; idx < 128 * 16; idx += 256) {
            const int row = idx >> 4;
            const int c8  = (idx & 15) << 3;
            const int node = m0 + row;
            uint4 v = make_uint4(0, 0, 0, 0);
            if (node < M)
                v = *(const uint4*)(Asrc + (size_t)node * 128 + c8);
            *(uint4*)&sA[row * SA_STRIDE + c8] = v;
        }
        __syncthreads();

        #pragma unroll 1
        for (int kt = 0; kt < 8; ++kt) {
            const int kk  = kt * 16;
            const int ktg = s * 8 + kt;

            uint2 bf[8];
            #pragma unroll
            for (int ni = 0; ni < 8; ++ni) {
                const int n = noff + ni * 8 + g;
                bf[ni] = g_Upk[(ktg * 128 + n) * 4 + tq];
            }

            uint32_t af[2][4];
            #pragma unroll
            for (int mi = 0; mi < 2; ++mi)
                #pragma unroll
                for (int h = 0; h < 2; ++h) {
                    const int srow = moff + mi * 16 + h * 8 + g;
                    #pragma unroll
                    for (int kh = 0; kh < 2; ++kh) {
                        const int off = srow * SA_STRIDE + kk + tq * 2 + kh * 8;
                        af[mi][kh * 2 + h] = *(const uint32_t*)&sA[off];
                    }
                }

            #pragma unroll
            for (int mi = 0; mi < 2; ++mi)
                #pragma unroll
                for (int ni = 0; ni < 8; ++ni) {
                    uint32_t b2r[2] = {bf[ni].x, bf[ni].y};
                    mma16816h(acc[mi][ni], af[mi], b2r);
                }
        }
    }

    #pragma unroll
    for (int ni = 0; ni < 8; ++ni) {
        const int col = noff + ni * 8 + tq * 2;
        const float2 cc = *(const float2*)(g_c + col);
        const float2 dd = *(const float2*)(g_d + col);
        #pragma unroll
        for (int mi = 0; mi < 2; ++mi)
            #pragma unroll
            for (int h = 0; h < 2; ++h) {
                const int r = mi * 2 + h;
                if (rowok[r]) {
                    float* p = out + (size_t)rows[r] * 128 + col;
                    float2 o;
                    if (WRITE) {
                        o.x = acc[mi][ni][h * 2 + 0] + cc.x + flag[r] * dd.x;
                        o.y = acc[mi][ni][h * 2 + 1] + cc.y + flag[r] * dd.y;
                    } else {
                        float2 prev = *(const float2*)p;
                        o.x = prev.x + acc[mi][ni][h * 2 + 0];
                        o.y = prev.y + acc[mi][ni][h * 2 + 1];
                    }
                    *(float2*)p = o;
                }
            }
    }
}

// gemm_x: out = xh @ U3^T + c + flag*d   (segment 2 only) — PROFILED SLOT
__global__ __launch_bounds__(256)
void gemm_x_kernel(float* __restrict__ out, int M) {
    gemm_body<2, 3, true>(nullptr, nullptr, g_xh, out, M);
}

// gemm_acc: out += A2h @ U1^T + m1h @ U2^T   (segments 0,1)
__global__ __launch_bounds__(256)
void gemm_acc_kernel(float* __restrict__ out, int M) {
    gemm_body<0, 2, false>(g_A2h, g_m1h, nullptr, out, M);
}

// ---------------------------------------------------------------------------
// Launch (8 kernels; slot 4 = gemm_x)
// ---------------------------------------------------------------------------
extern "C" void kernel_launch(void* const* d_in, const int* in_sizes, int n_in,
                              void* d_out, int out_size) {
    const float* x    = (const float*)d_in[0];
    const void*  eidx = d_in[1];
    const float* W_l1 = (const float*)d_in[2];
    const float* b_l1 = (const float*)d_in[3];
    const float* W_r1 = (const float*)d_in[4];
    const float* W_l2 = (const float*)d_in[5];
    const float* b_l2 = (const float*)d_in[6];
    const float* W_r2 = (const float*)d_in[7];
    float* out = (float*)d_out;

    __half *p_xh, *p_m1h, *p_A2h;
    cudaGetSymbolAddress((void**)&p_xh,  g_xh);
    cudaGetSymbolAddress((void**)&p_m1h, g_m1h);
    cudaGetSymbolAddress((void**)&p_A2h, g_A2h);

    // 1) count + x->fp16 convert
    count_conv_kernel<<<CONV_BLOCKS, 256>>>(eidx, x);
    // 2) scanA + weights
    scanAW_kernel<<<SCAN_BLOCKS + WEIGHT_BLOCKS, 256>>>(W_l1, W_r1, W_l2, W_r2, b_l1, b_l2);
    // 3) scanC2
    scanC2_kernel<<<SCAN_BLOCKS, 256>>>();
    // 4) gemm_x  [profiled]
    gemm_x_kernel<<<(N_NODES + 127) / 128, 256, SMEM_BYTES>>>(out, N_NODES);
    // 5) fill (8 edges/thread)
    fill_csr_kernel<<<(N_EDGES / 8 + 255) / 256, 256>>>(eidx);
    // 6-7) gathers (fp16)
    const unsigned gblocks = (N_NODES * 32 + 255) / 256;
    gather_kernel<<<gblocks, 256>>>(p_xh, p_m1h);
    gather_kernel<<<gblocks, 256>>>(p_m1h, p_A2h);
    // 8) gemm accumulate (segments 0,1)
    gemm_acc_kernel<<<(N_NODES + 127) / 128, 256, SMEM_BYTES>>>(out, N_NODES);
}

// round 17
// speedup vs baseline: 1.1151x; 1.1151x over previous
#include <cuda_runtime.h>
#include <cuda_fp16.h>
#include <cstdint>
#include <cstddef>

// Problem constants (match reference)
#define N_NODES 50000
#define N_EDGES 800000
#define D_IN    128
#define D_HID   256
#define D_OUT   128

// ---------------------------------------------------------------------------
// Pipeline (7 launches; all node features fp16 after conversion):
//   count+conv : dst histogram (8 edges/thr) + x -> fp16 g_xh
//   scanAW     : blocks 0..195 per-block sums -> g_bsum; blocks 196.. weights
//   scanC2     : per-block prefix of g_bsum + local scan -> metadata; clean cnt
//   fill       : CSR adjacency, 8 edges/thread
//   gather1    : m1h[n] = fp16( invdeg[n] * sum xh[s] )   (fp32 accum)
//   gather2    : A2h[n] = fp16( invdeg[n] * sum m1h[s] )
//   gemm       : out = A2h@U1^T + m1h@U2^T + xh@U3^T + c + flag*d
//                (mma.sync fp16; B fragments software-pipelined)
// ---------------------------------------------------------------------------

#define SCAN_BLOCKS ((N_NODES + 255) / 256)   // 196

// Device scratch
__device__ int    g_cnt[N_NODES];         // zero at load; scanC2 re-zeroes per replay
__device__ int    g_bsum[SCAN_BLOCKS];
__device__ int    g_rowoff[N_NODES + 1];
__device__ int    g_cursor[N_NODES];
__device__ int    g_eadj[N_EDGES];
__device__ float  g_invdeg[N_NODES];
__device__ float  g_flag[N_NODES];
__device__ __half g_xh[(size_t)N_NODES * 128];
__device__ __half g_m1h[(size_t)N_NODES * 128];
__device__ __half g_A2h[(size_t)N_NODES * 128];
// B fragments, warp-coalesced: index = (ktg*128 + n)*4 + tq
__device__ uint2  g_Upk[24 * 128 * 4];
__device__ float  g_c[128];
__device__ float  g_d[128];

// smem tile geometry (half): 128 rows x 128 cols, stride 136 (single buffer)
#define SA_STRIDE 136
#define SMEM_BYTES (128 * SA_STRIDE * 2)   // 34816 B

// ---------------------------------------------------------------------------
// helpers
// ---------------------------------------------------------------------------
__device__ __forceinline__ void mma16816h(float* d, const uint32_t* a, const uint32_t* b) {
    asm volatile(
        "mma.sync.aligned.m16n8k16.row.col.f32.f16.f16.f32 "
        "{%0,%1,%2,%3}, {%4,%5,%6,%7}, {%8,%9}, {%0,%1,%2,%3};"
        : "+f"(d[0]), "+f"(d[1]), "+f"(d[2]), "+f"(d[3])
        : "r"(a[0]), "r"(a[1]), "r"(a[2]), "r"(a[3]), "r"(b[0]), "r"(b[1]));
}
__device__ __forceinline__ uint32_t packh2(float a, float b) {
    __half2 h = __float22half2_rn(make_float2(a, b));
    return *reinterpret_cast<uint32_t*>(&h);
}
__device__ __forceinline__ float2 unpackh2(uint32_t u) {
    __half2 h = *reinterpret_cast<__half2*>(&u);
    return __half22float2(h);
}

// Per-block idx-dtype detection (int32 read as int64 -> >= 2^32 a.s.)
__device__ __forceinline__ int detect_idx64_block(const void* eidx) {
    __shared__ int s_idx64;
    if (threadIdx.x < 32) {
        const long long* p = (const long long*)eidx;
        int ok = 1;
        #pragma unroll
        for (int i = 0; i < 16; ++i) {
            long long v = p[threadIdx.x * 16 + i];
            ok &= (v >= 0 && v < (long long)N_NODES);
        }
        unsigned m = __ballot_sync(0xffffffffu, ok);
        if (threadIdx.x == 0) s_idx64 = (m == 0xffffffffu) ? 1 : 0;
    }
    __syncthreads();
    return s_idx64;
}

// load 8 indices starting at e0 (e0 multiple of 8, in-bounds)
__device__ __forceinline__ void load8_idx(const void* base, int idx64, long long off,
                                          int e0, int* d) {
    if (idx64) {
        const long long* ep = (const long long*)base + off;
        const longlong2* p = (const longlong2*)(ep + e0);
        longlong2 a = p[0], b = p[1], c = p[2], e = p[3];
        d[0] = (int)a.x; d[1] = (int)a.y; d[2] = (int)b.x; d[3] = (int)b.y;
        d[4] = (int)c.x; d[5] = (int)c.y; d[6] = (int)e.x; d[7] = (int)e.y;
    } else {
        const int* ep = (const int*)base + off;
        const int4 a = *(const int4*)(ep + e0);
        const int4 b = *(const int4*)(ep + e0 + 4);
        d[0] = a.x; d[1] = a.y; d[2] = a.z; d[3] = a.w;
        d[4] = b.x; d[5] = b.y; d[6] = b.z; d[7] = b.w;
    }
}

// ---------------------------------------------------------------------------
// count + convert
// ---------------------------------------------------------------------------
#define CONV_BLOCKS 3125   // 1.6M float4 groups / (256 thr * 2)
#define EDGE_BLOCKS8 ((N_EDGES / 8 + 255) / 256)   // 391

__global__ __launch_bounds__(256)
void count_conv_kernel(const void* __restrict__ eidx, const float* __restrict__ x) {
    const int idx64 = detect_idx64_block(eidx);
    const int tid = blockIdx.x * 256 + threadIdx.x;

    const float4* x4 = (const float4*)x;
    #pragma unroll
    for (int j = 0; j < 2; ++j) {
        const int gidx = tid + j * (CONV_BLOCKS * 256);
        if (gidx < (N_NODES * 128) / 4) {
            float4 v = x4[gidx];
            uint2 h;
            h.x = packh2(v.x, v.y);
            h.y = packh2(v.z, v.w);
            ((uint2*)g_xh)[gidx] = h;
        }
    }

    if (blockIdx.x < EDGE_BLOCKS8) {
        const int e0 = tid * 8;
        if (e0 < N_EDGES) {
            int d[8];
            load8_idx(eidx, idx64, N_EDGES, e0, d);
            #pragma unroll
            for (int j = 0; j < 8; ++j) atomicAdd(&g_cnt[d[j]], 1);
        }
    }
}

// ---------------------------------------------------------------------------
// scanAW: blocks 0..195 per-block sums; blocks 196.. weight pre-products
// ---------------------------------------------------------------------------
#define WEIGHT_ITEMS (128 * 96 + 128)                  // 12416
#define WEIGHT_BLOCKS ((WEIGHT_ITEMS + 255) / 256)     // 49

__global__ __launch_bounds__(256)
void scanAW_kernel(const float* __restrict__ Wl1,
                   const float* __restrict__ Wr1,
                   const float* __restrict__ Wl2,
                   const float* __restrict__ Wr2,
                   const float* __restrict__ b1,
                   const float* __restrict__ b2) {
    if (blockIdx.x < SCAN_BLOCKS) {
        __shared__ int ws[8];
        const int node = blockIdx.x * 256 + threadIdx.x;
        int v = (node < N_NODES) ? g_cnt[node] : 0;
        #pragma unroll
        for (int d = 16; d > 0; d >>= 1) v += __shfl_down_sync(0xffffffffu, v, d);
        if ((threadIdx.x & 31) == 0) ws[threadIdx.x >> 5] = v;
        __syncthreads();
        if (threadIdx.x < 8) {
            int s = ws[threadIdx.x];
            #pragma unroll
            for (int d = 4; d > 0; d >>= 1) s += __shfl_down_sync(0xffu, s, d);
            if (threadIdx.x == 0) g_bsum[blockIdx.x] = s;
        }
        return;
    }

    const int tid = (blockIdx.x - SCAN_BLOCKS) * 256 + threadIdx.x;
    if (tid < 128 * 96) {
        const int n   = tid / 96;
        const int rem = tid - n * 96;
        const int ktg = rem >> 2;
        const int tq  = rem & 3;
        const int seg = ktg >> 3;
        const int k0  = (ktg & 7) * 16 + 2 * tq;

        float u[4] = {0.f, 0.f, 0.f, 0.f};
        const float* A1 = Wl2 + (size_t)n * 256;
        const float* A2 = Wr2 + (size_t)n * 256;
        #pragma unroll 4
        for (int t = 0; t < 256; ++t) {
            const float wl2 = A1[t];
            const float wr2 = A2[t];
            const float* rl = Wl1 + (size_t)t * 128 + k0;
            const float* rr = Wr1 + (size_t)t * 128 + k0;
            if (seg == 0) {
                u[0] += wl2 * rl[0]; u[1] += wl2 * rl[1];
                u[2] += wl2 * rl[8]; u[3] += wl2 * rl[9];
            } else if (seg == 1) {
                u[0] += wl2 * rr[0] + wr2 * rl[0];
                u[1] += wl2 * rr[1] + wr2 * rl[1];
                u[2] += wl2 * rr[8] + wr2 * rl[8];
                u[3] += wl2 * rr[9] + wr2 * rl[9];
            } else {
                u[0] += wr2 * rr[0]; u[1] += wr2 * rr[1];
                u[2] += wr2 * rr[8]; u[3] += wr2 * rr[9];
            }
        }
        g_Upk[(ktg * 128 + n) * 4 + tq] =
            make_uint2(packh2(u[0], u[1]), packh2(u[2], u[3]));
    } else if (tid < WEIGHT_ITEMS) {
        const int a = tid - 128 * 96;
        float c = 0.f, d = 0.f;
        #pragma unroll 4
        for (int k = 0; k < 256; ++k) {
            c += Wr2[a * 256 + k] * b1[k];
            d += Wl2[a * 256 + k] * b1[k];
        }
        g_c[a] = b2[a] + c;
        g_d[a] = d;
    }
}

// ---------------------------------------------------------------------------
// scanC2: per-block prefix of g_bsum + local exclusive scan + metadata
// ---------------------------------------------------------------------------
__global__ __launch_bounds__(256)
void scanC2_kernel() {
    __shared__ int sc[256];
    __shared__ int s_boff;
    const int t = threadIdx.x;

    {
        int p = 0;
        for (int j = t; j < blockIdx.x; j += 256) p += g_bsum[j];
        #pragma unroll
        for (int d = 16; d > 0; d >>= 1) p += __shfl_down_sync(0xffffffffu, p, d);
        sc[t] = 0;
        __syncthreads();
        if ((t & 31) == 0) sc[t >> 5] = p;
        __syncthreads();
        if (t == 0) {
            int s = 0;
            #pragma unroll
            for (int w = 0; w < 8; ++w) s += sc[w];
            s_boff = s;
        }
        __syncthreads();
    }

    const int node = blockIdx.x * 256 + t;
    const int c = (node < N_NODES) ? g_cnt[node] : 0;
    sc[t] = c;
    __syncthreads();
    #pragma unroll
    for (int d = 1; d < 256; d <<= 1) {
        int add = (t >= d) ? sc[t - d] : 0;
        __syncthreads();
        sc[t] += add;
        __syncthreads();
    }
    if (node < N_NODES) {
        const int off = s_boff + sc[t] - c;
        g_rowoff[node] = off;
        g_cursor[node] = off;
        g_invdeg[node] = 1.0f / fmaxf((float)c, 1.0f);
        g_flag[node]   = (c > 0) ? 1.0f : 0.0f;
        g_cnt[node]    = 0;
    }
    if (node == N_NODES - 1) g_rowoff[N_NODES] = N_EDGES;
}

// ---------------------------------------------------------------------------
// fill: CSR adjacency, 8 edges per thread
// ---------------------------------------------------------------------------
__global__ __launch_bounds__(256)
void fill_csr_kernel(const void* __restrict__ eidx) {
    const int idx64 = detect_idx64_block(eidx);
    const int e0 = (blockIdx.x * blockDim.x + threadIdx.x) * 8;
    if (e0 >= N_EDGES) return;
    int s[8], d[8];
    load8_idx(eidx, idx64, 0, e0, s);
    load8_idx(eidx, idx64, N_EDGES, e0, d);
    int pos[8];
    #pragma unroll
    for (int j = 0; j < 8; ++j) pos[j] = atomicAdd(&g_cursor[d[j]], 1);
    #pragma unroll
    for (int j = 0; j < 8; ++j) g_eadj[pos[j]] = s[j];
}

// ---------------------------------------------------------------------------
// Gather (fp16 in/out, fp32 accum): one warp per node, lane owns 4 columns
// ---------------------------------------------------------------------------
__global__ __launch_bounds__(256)
void gather_kernel(const __half* __restrict__ src_feat, __half* __restrict__ dst_feat) {
    const int node = (blockIdx.x * blockDim.x + threadIdx.x) >> 5;
    if (node >= N_NODES) return;
    const int lane = threadIdx.x & 31;
    const int beg = g_rowoff[node];
    const int end = g_rowoff[node + 1];
    const uint2* f2 = (const uint2*)src_feat;

    float4 acc = make_float4(0.f, 0.f, 0.f, 0.f);
    int i = beg;
    for (; i + 4 <= end; i += 4) {
        const int s0 = g_eadj[i];
        const int s1 = g_eadj[i + 1];
        const int s2 = g_eadj[i + 2];
        const int s3 = g_eadj[i + 3];
        uint2 u0 = __ldg(&f2[(size_t)s0 * 32 + lane]);
        uint2 u1 = __ldg(&f2[(size_t)s1 * 32 + lane]);
        uint2 u2 = __ldg(&f2[(size_t)s2 * 32 + lane]);
        uint2 u3 = __ldg(&f2[(size_t)s3 * 32 + lane]);
        float2 a, b;
        a = unpackh2(u0.x); b = unpackh2(u0.y);
        acc.x += a.x; acc.y += a.y; acc.z += b.x; acc.w += b.y;
        a = unpackh2(u1.x); b = unpackh2(u1.y);
        acc.x += a.x; acc.y += a.y; acc.z += b.x; acc.w += b.y;
        a = unpackh2(u2.x); b = unpackh2(u2.y);
        acc.x += a.x; acc.y += a.y; acc.z += b.x; acc.w += b.y;
        a = unpackh2(u3.x); b = unpackh2(u3.y);
        acc.x += a.x; acc.y += a.y; acc.z += b.x; acc.w += b.y;
    }
    for (; i < end; ++i) {
        const int s0 = g_eadj[i];
        uint2 u0 = __ldg(&f2[(size_t)s0 * 32 + lane]);
        float2 a = unpackh2(u0.x), b = unpackh2(u0.y);
        acc.x += a.x; acc.y += a.y; acc.z += b.x; acc.w += b.y;
    }
    const float w = g_invdeg[node];
    uint2 o;
    o.x = packh2(acc.x * w, acc.y * w);
    o.y = packh2(acc.z * w, acc.w * w);
    ((uint2*)dst_feat)[(size_t)node * 32 + lane] = o;
}

// ---------------------------------------------------------------------------
// Tensor-core GEMM (single smem A tile per segment; B fragments pipelined
// one k-step ahead so their global-load latency overlaps the MMAs):
// out[M,128] = [A2h | m1h | xh] @ U^T + c + flag*d
// ---------------------------------------------------------------------------
__global__ __launch_bounds__(256)
void mma_gemm_kernel(float* __restrict__ out, int M) {
    extern __shared__ __half sA[];

    const int tid  = threadIdx.x;
    const int wid  = tid >> 5;
    const int lane = tid & 31;
    const int g    = lane >> 2;
    const int tq   = lane & 3;
    const int m0   = blockIdx.x * 128;
    const int moff = (wid >> 1) * 32;
    const int noff = (wid & 1) * 64;

    int   rows[4];
    bool  rowok[4];
    float flag[4];
    #pragma unroll
    for (int r = 0; r < 4; ++r) {
        const int mi = r >> 1, h = r & 1;
        rows[r]  = m0 + moff + mi * 16 + h * 8 + g;
        rowok[r] = rows[r] < M;
        flag[r]  = rowok[r] ? g_flag[rows[r]] : 0.f;
    }

    float acc[2][8][4];
    #pragma unroll
    for (int mi = 0; mi < 2; ++mi)
        #pragma unroll
        for (int ni = 0; ni < 8; ++ni)
            #pragma unroll
            for (int q = 0; q < 4; ++q) acc[mi][ni][q] = 0.f;

    // B fragment pointer for this thread (indexed by ktg, ni)
    auto bload = [&](int ktg, uint2* bf) {
        #pragma unroll
        for (int ni = 0; ni < 8; ++ni) {
            const int n = noff + ni * 8 + g;
            bf[ni] = g_Upk[(ktg * 128 + n) * 4 + tq];
        }
    };

    uint2 bf_cur[8], bf_nxt[8];
    bload(0, bf_cur);   // prefetch first k-step of segment 0

    #pragma unroll 1
    for (int s = 0; s < 3; ++s) {
        const __half* Asrc = (s == 0) ? g_A2h : ((s == 1) ? g_m1h : g_xh);

        if (s > 0) __syncthreads();
        #pragma unroll 4
        for (int idx = tid; idx < 128 * 16; idx += 256) {
            const int row = idx >> 4;
            const int c8  = (idx & 15) << 3;
            const int node = m0 + row;
            uint4 v = make_uint4(0, 0, 0, 0);
            if (node < M)
                v = *(const uint4*)(Asrc + (size_t)node * 128 + c8);
            *(uint4*)&sA[row * SA_STRIDE + c8] = v;
        }
        __syncthreads();

        #pragma unroll 1
        for (int kt = 0; kt < 8; ++kt) {
            const int kk  = kt * 16;
            const int ktg = s * 8 + kt;

            // prefetch next k-step's B fragments (crosses segment boundary)
            if (ktg < 23) bload(ktg + 1, bf_nxt);

            // A fragments: LDS
            uint32_t af[2][4];
            #pragma unroll
            for (int mi = 0; mi < 2; ++mi)
                #pragma unroll
                for (int h = 0; h < 2; ++h) {
                    const int srow = moff + mi * 16 + h * 8 + g;
                    #pragma unroll
                    for (int kh = 0; kh < 2; ++kh) {
                        const int off = srow * SA_STRIDE + kk + tq * 2 + kh * 8;
                        af[mi][kh * 2 + h] = *(const uint32_t*)&sA[off];
                    }
                }

            #pragma unroll
            for (int mi = 0; mi < 2; ++mi)
                #pragma unroll
                for (int ni = 0; ni < 8; ++ni) {
                    uint32_t b2r[2] = {bf_cur[ni].x, bf_cur[ni].y};
                    mma16816h(acc[mi][ni], af[mi], b2r);
                }

            #pragma unroll
            for (int ni = 0; ni < 8; ++ni) bf_cur[ni] = bf_nxt[ni];
        }
    }

    #pragma unroll
    for (int ni = 0; ni < 8; ++ni) {
        const int col = noff + ni * 8 + tq * 2;
        const float2 cc = *(const float2*)(g_c + col);
        const float2 dd = *(const float2*)(g_d + col);
        #pragma unroll
        for (int mi = 0; mi < 2; ++mi)
            #pragma unroll
            for (int h = 0; h < 2; ++h) {
                const int r = mi * 2 + h;
                if (rowok[r]) {
                    float2 o;
                    o.x = acc[mi][ni][h * 2 + 0] + cc.x + flag[r] * dd.x;
                    o.y = acc[mi][ni][h * 2 + 1] + cc.y + flag[r] * dd.y;
                    *(float2*)(out + (size_t)rows[r] * 128 + col) = o;
                }
            }
    }
}

// ---------------------------------------------------------------------------
// Launch (7 kernels)
// ---------------------------------------------------------------------------
extern "C" void kernel_launch(void* const* d_in, const int* in_sizes, int n_in,
                              void* d_out, int out_size) {
    const float* x    = (const float*)d_in[0];
    const void*  eidx = d_in[1];
    const float* W_l1 = (const float*)d_in[2];
    const float* b_l1 = (const float*)d_in[3];
    const float* W_r1 = (const float*)d_in[4];
    const float* W_l2 = (const float*)d_in[5];
    const float* b_l2 = (const float*)d_in[6];
    const float* W_r2 = (const float*)d_in[7];
    float* out = (float*)d_out;

    __half *p_xh, *p_m1h, *p_A2h;
    cudaGetSymbolAddress((void**)&p_xh,  g_xh);
    cudaGetSymbolAddress((void**)&p_m1h, g_m1h);
    cudaGetSymbolAddress((void**)&p_A2h, g_A2h);

    // 1) count + x->fp16 convert
    count_conv_kernel<<<CONV_BLOCKS, 256>>>(eidx, x);
    // 2) scanA + weights
    scanAW_kernel<<<SCAN_BLOCKS + WEIGHT_BLOCKS, 256>>>(W_l1, W_r1, W_l2, W_r2, b_l1, b_l2);
    // 3) scanC2
    scanC2_kernel<<<SCAN_BLOCKS, 256>>>();
    // 4) fill (8 edges/thread)
    fill_csr_kernel<<<(N_EDGES / 8 + 255) / 256, 256>>>(eidx);
    // 5-6) gathers (fp16)
    const unsigned gblocks = (N_NODES * 32 + 255) / 256;
    gather_kernel<<<gblocks, 256>>>(p_xh, p_m1h);
    gather_kernel<<<gblocks, 256>>>(p_m1h, p_A2h);
    // 7) fused tensor-core GEMM (B pipelined)
    mma_gemm_kernel<<<(N_NODES + 127) / 128, 256, SMEM_BYTES>>>(out, N_NODES);
}